// round 7
// baseline (speedup 1.0000x reference)
#include <cuda_runtime.h>

// Problem constants
#define BATCH    32
#define CH       2048
#define SZ       4096

// Block decomposition: 8 c-groups x 32 s-threads = 256 threads.
// Each block produces FINAL outputs for a (128 s-cols x 4 batches) tile:
// c is split across the 8 warp-groups and reduced through shared memory,
// so no global partials / second kernel / inter-CTA sync is needed.
#define C_GROUPS   8
#define S_THREADS  32
#define TPB        (C_GROUPS * S_THREADS)     // 256
#define CCHUNK     (CH / C_GROUPS)            // 256 c-iterations per group
#define BG         4                          // batches per block (w L2 reuse)
#define S_PER_BLOCK (S_THREADS * 4)           // 128 s-columns per block

// Streaming load (evict-first): 1 GiB of x must not thrash w out of L2
__device__ __forceinline__ float4 ldcs4(const float* p) {
    float4 v;
    asm volatile("ld.global.cs.v4.f32 {%0,%1,%2,%3}, [%4];"
                 : "=f"(v.x), "=f"(v.y), "=f"(v.z), "=f"(v.w) : "l"(p));
    return v;
}

__global__ __launch_bounds__(TPB) void CWG_fused_kernel(
    const float* __restrict__ x,
    const float* __restrict__ w,
    const float* __restrict__ bias,
    float* __restrict__ out)
{
    const int s_t = threadIdx.x & (S_THREADS - 1);   // 0..31 (lane == s position)
    const int cg  = threadIdx.x >> 5;                // 0..7  (c-group == warp id)
    const int s0  = blockIdx.y * S_PER_BLOCK + s_t * 4;
    const int b0  = blockIdx.x * BG;                 // batch fastest-varying:
    const int c0  = cg * CCHUNK;                     // same-w blocks co-scheduled

    float4 acc[BG];
#pragma unroll
    for (int b = 0; b < BG; b++) acc[b] = make_float4(0.f, 0.f, 0.f, 0.f);

    const float* wp = w + (size_t)c0 * SZ + s0;
    const float* xp = x + ((size_t)b0 * CH + (size_t)c0) * SZ + s0;

#pragma unroll 4
    for (int c = 0; c < CCHUNK; c++) {
        const float4 wv = __ldg((const float4*)(wp + (size_t)c * SZ));
#pragma unroll
        for (int b = 0; b < BG; b++) {
            const float4 xv = ldcs4(xp + ((size_t)b * CH + (size_t)c) * SZ);
            acc[b].x = fmaf(xv.x, wv.x, acc[b].x);
            acc[b].y = fmaf(xv.y, wv.y, acc[b].y);
            acc[b].z = fmaf(xv.z, wv.z, acc[b].z);
            acc[b].w = fmaf(xv.w, wv.w, acc[b].w);
        }
    }

    // ---- intra-block c-group reduction via shared memory (16 KB) ----
    __shared__ float4 smem[C_GROUPS][S_THREADS][BG];
#pragma unroll
    for (int b = 0; b < BG; b++)
        smem[cg][s_t][b] = acc[b];
    __syncthreads();

    // 128 worker threads: one (s-position, batch) output each.
    const int wk = threadIdx.x;
    if (wk < S_THREADS * BG) {
        const int b  = wk >> 5;            // 0..3
        const int st = wk & (S_THREADS - 1);
        float4 sum = make_float4(0.f, 0.f, 0.f, 0.f);
#pragma unroll
        for (int g = 0; g < C_GROUPS; g++) {   // fixed order => deterministic
            const float4 p = smem[g][st][b];
            sum.x += p.x; sum.y += p.y; sum.z += p.z; sum.w += p.w;
        }
        const int sc = blockIdx.y * S_PER_BLOCK + st * 4;
        const float4 bv = *(const float4*)(bias + sc);
        float4 r;
        r.x = fmaxf(sum.x + bv.x, 0.f);
        r.y = fmaxf(sum.y + bv.y, 0.f);
        r.z = fmaxf(sum.z + bv.z, 0.f);
        r.w = fmaxf(sum.w + bv.w, 0.f);
        *(float4*)(out + (size_t)(b0 + b) * SZ + sc) = r;
    }
}

extern "C" void kernel_launch(void* const* d_in, const int* in_sizes, int n_in,
                              void* d_out, int out_size)
{
    const float* x    = (const float*)d_in[0];
    const float* w    = (const float*)d_in[1];
    const float* bias = (const float*)d_in[2];
    float* out        = (float*)d_out;

    // 8 batch-groups (fastest) x 32 s-tiles = 256 blocks, all co-resident.
    dim3 grid(BATCH / BG, SZ / S_PER_BLOCK);
    CWG_fused_kernel<<<grid, TPB>>>(x, w, bias, out);
}

// round 8
// speedup vs baseline: 1.3032x; 1.3032x over previous
#include <cuda_runtime.h>

// Problem constants
#define BATCH    32
#define CH       2048
#define SZ       4096
#define CSPLIT   16                 // c-dimension splits
#define CCHUNK   (CH / CSPLIT)      // 128 c iterations per block
#define BG       4                  // batches per block (w reuse factor)
#define TPB      128                // threads per block
#define S_PER_BLOCK (TPB * 4)       // 512 s-columns per block (float4/thread)

// 16 * 32 * 4096 floats = 8 MB partial-sum scratch
__device__ float g_partial[CSPLIT * BATCH * SZ];

// Streaming load (evict-first): 1 GiB of x must not thrash w out of L2
__device__ __forceinline__ float4 ldcs4(const float* p) {
    float4 v;
    asm volatile("ld.global.cs.v4.f32 {%0,%1,%2,%3}, [%4];"
                 : "=f"(v.x), "=f"(v.y), "=f"(v.z), "=f"(v.w) : "l"(p));
    return v;
}

// ============ streaming stage: UNCHANGED from the 158.5us R6 kernel ============
__global__ __launch_bounds__(TPB) void CWG_partial_kernel(
    const float* __restrict__ x,
    const float* __restrict__ w)
{
    const int s0  = blockIdx.x * S_PER_BLOCK + threadIdx.x * 4;
    const int b0  = blockIdx.y * BG;
    const int cs  = blockIdx.z;
    const int c0  = cs * CCHUNK;

    float4 acc[BG];
#pragma unroll
    for (int b = 0; b < BG; b++) acc[b] = make_float4(0.f, 0.f, 0.f, 0.f);

    const float* wp = w + (size_t)c0 * SZ + s0;
    const float* xp = x + ((size_t)b0 * CH + (size_t)c0) * SZ + s0;

#pragma unroll 4
    for (int c = 0; c < CCHUNK; c++) {
        const float4 wv = __ldg((const float4*)(wp + (size_t)c * SZ));
#pragma unroll
        for (int b = 0; b < BG; b++) {
            const float4 xv = ldcs4(xp + ((size_t)b * CH + (size_t)c) * SZ);
            acc[b].x = fmaf(xv.x, wv.x, acc[b].x);
            acc[b].y = fmaf(xv.y, wv.y, acc[b].y);
            acc[b].z = fmaf(xv.z, wv.z, acc[b].z);
            acc[b].w = fmaf(xv.w, wv.w, acc[b].w);
        }
    }

#pragma unroll
    for (int b = 0; b < BG; b++) {
        *(float4*)(g_partial + ((size_t)cs * BATCH + (size_t)(b0 + b)) * SZ + s0) = acc[b];
    }
}

// ============ finalize: 4 lanes cooperate per output (4x parallelism) ============
__global__ __launch_bounds__(256) void CWG_finalize_kernel(
    const float* __restrict__ bias,
    float* __restrict__ out)
{
    // 512 blocks x 256 threads = 131072 threads; 4 threads per float4 output.
    const int tid = blockIdx.x * 256 + threadIdx.x;
    const int i4  = tid >> 2;            // output float4 index (0..32767)
    const int kq  = tid & 3;             // k-quarter handled by this lane
    const int i   = i4 * 4;              // float index into [BATCH*SZ]
    const int s   = i & (SZ - 1);

    // 4 independent DRAM loads per thread (partials are DRAM-resident; .cs)
    float4 sum = make_float4(0.f, 0.f, 0.f, 0.f);
#pragma unroll
    for (int j = 0; j < 4; j++) {
        const int k = kq * 4 + j;
        const float4 p = ldcs4(g_partial + (size_t)k * BATCH * SZ + i);
        sum.x += p.x; sum.y += p.y; sum.z += p.z; sum.w += p.w;
    }

    // butterfly reduce across the 4 lanes of this quad (fixed lane mapping
    // and fixed tree shape => deterministic across graph replays)
#pragma unroll
    for (int d = 1; d < 4; d <<= 1) {
        sum.x += __shfl_xor_sync(0xffffffffu, sum.x, d);
        sum.y += __shfl_xor_sync(0xffffffffu, sum.y, d);
        sum.z += __shfl_xor_sync(0xffffffffu, sum.z, d);
        sum.w += __shfl_xor_sync(0xffffffffu, sum.w, d);
    }

    if (kq == 0) {
        const float4 bv = *(const float4*)(bias + s);
        float4 r;
        r.x = fmaxf(sum.x + bv.x, 0.f);
        r.y = fmaxf(sum.y + bv.y, 0.f);
        r.z = fmaxf(sum.z + bv.z, 0.f);
        r.w = fmaxf(sum.w + bv.w, 0.f);
        *(float4*)(out + i) = r;
    }
}

extern "C" void kernel_launch(void* const* d_in, const int* in_sizes, int n_in,
                              void* d_out, int out_size)
{
    const float* x    = (const float*)d_in[0];
    const float* w    = (const float*)d_in[1];
    const float* bias = (const float*)d_in[2];
    float* out        = (float*)d_out;

    dim3 grid(SZ / S_PER_BLOCK, BATCH / BG, CSPLIT);  // (8, 8, 16) = 1024 blocks
    CWG_partial_kernel<<<grid, TPB>>>(x, w);

    // BATCH*SZ floats -> 32768 float4 outputs -> 131072 threads -> 512 blocks
    CWG_finalize_kernel<<<512, 256>>>(bias, out);
}